// round 12
// baseline (speedup 1.0000x reference)
#include <cuda_runtime.h>
#include <cuda_fp16.h>
#include <cstdint>
#include <math.h>

#define BB 16
#define CC 512
#define SS 1024
#define PER_B (CC*SS)

typedef __half f16;

// ---------------- scratch (__device__ globals; no allocs) ----------------
__device__ float g_psum[BB*64], g_psq[BB*64], g_stats[BB*2];
__device__ unsigned g_ctr;
__device__ f16  g_h2 [(size_t)BB*SS*512];    // norm'd [B*S, C] fp16 (A-side)
__device__ f16  g_w1 [1536*512];             // qkv_w fp16 (B-side)
__device__ f16  g_w2 [512*512];              // proj_w fp16 (A-side for proj)
__device__ f16  g_q2 [(size_t)BB*SS*512];    // Q*scale fp16 (A-side)
__device__ f16  g_k2 [(size_t)BB*SS*512];    // K fp16 (B-side)
__device__ f16  g_v2 [(size_t)BB*CC*1024];   // V transposed [B,C,S] fp16 (B-side)
__device__ f16  g_ao2[(size_t)BB*SS*512];    // attn out fp16 (B-side for proj)

// ---------------- helpers ----------------
__device__ __forceinline__ uint32_t smem_u32(const void* p) {
    uint32_t a;
    asm("{ .reg .u64 t; cvta.to.shared.u64 t, %1; cvt.u32.u64 %0, t; }" : "=r"(a) : "l"(p));
    return a;
}
#define CP_ASYNC16(dst, src) \
    asm volatile("cp.async.cg.shared.global [%0], [%1], 16;" :: "r"(dst), "l"(src) : "memory")
#define CP_COMMIT() asm volatile("cp.async.commit_group;" ::: "memory")
#define CP_WAIT0()  asm volatile("cp.async.wait_group 0;" ::: "memory")
#define CP_WAIT1()  asm volatile("cp.async.wait_group 1;" ::: "memory")
#define CP_WAIT2()  asm volatile("cp.async.wait_group 2;" ::: "memory")
#define LDM_X4(r0,r1,r2,r3,addr) \
    asm volatile("ldmatrix.sync.aligned.m8n8.x4.shared.b16 {%0,%1,%2,%3}, [%4];" \
        : "=r"(r0),"=r"(r1),"=r"(r2),"=r"(r3) : "r"(addr))
#define MMA16816(d, a, b0, b1) \
    asm volatile("mma.sync.aligned.m16n8k16.row.col.f32.f16.f16.f32 " \
        "{%0,%1,%2,%3}, {%4,%5,%6,%7}, {%8,%9}, {%0,%1,%2,%3};" \
        : "+f"((d)[0]), "+f"((d)[1]), "+f"((d)[2]), "+f"((d)[3]) \
        : "r"((a)[0]), "r"((a)[1]), "r"((a)[2]), "r"((a)[3]), "r"(b0), "r"(b1))

// ---------------- weight convert (plain fp16) ----------------
__global__ void wconv(const float* __restrict__ w1s, const float* __restrict__ w2s) {
    int i = blockIdx.x * 256 + threadIdx.x;
    if (i < 2048*512) {
        if (i < 1536*512) g_w1[i] = __float2half_rn(w1s[i]);
        else              g_w2[i - 1536*512] = __float2half_rn(w2s[i - 1536*512]);
    }
}

// ---------------- fused GroupNorm stats ----------------
__global__ void gn_stats(const float* __restrict__ x) {
    int b = blockIdx.y, chunk = blockIdx.x, t = threadIdx.x;
    const float* p = x + (size_t)b*PER_B + (size_t)chunk*8192;
    float s = 0.f, q = 0.f;
#pragma unroll
    for (int i = 0; i < 32; i++) { float v = p[t + i*256]; s += v; q += v*v; }
    __shared__ float ss_[8], sq_[8];
    for (int o = 16; o > 0; o >>= 1) {
        s += __shfl_down_sync(0xffffffffu, s, o);
        q += __shfl_down_sync(0xffffffffu, q, o);
    }
    if ((t & 31) == 0) { ss_[t >> 5] = s; sq_[t >> 5] = q; }
    __syncthreads();
    __shared__ int isLast;
    if (t == 0) {
        float S2 = 0.f, Q2 = 0.f;
#pragma unroll
        for (int i = 0; i < 8; i++) { S2 += ss_[i]; Q2 += sq_[i]; }
        g_psum[b*64 + chunk] = S2; g_psq[b*64 + chunk] = Q2;
        __threadfence();
        unsigned v = atomicAdd(&g_ctr, 1u);
        isLast = (v == 64u*BB - 1u);
    }
    __syncthreads();
    if (isLast) {
        if (t < BB) {
            float s2 = 0.f, q2 = 0.f;
            for (int i = 0; i < 64; i++) { s2 += g_psum[t*64+i]; q2 += g_psq[t*64+i]; }
            float mean = s2 * (1.f/(float)PER_B);
            float var  = q2 * (1.f/(float)PER_B) - mean*mean;
            g_stats[2*t] = mean; g_stats[2*t+1] = rsqrtf(var + 1e-5f);
        }
        if (t == 0) g_ctr = 0u;
    }
}

// ---------------- normalize + transpose -> g_h2 [B*S, C] fp16 ----------------
__global__ void norm_split(const float* __restrict__ x,
                           const float* __restrict__ gw,
                           const float* __restrict__ gb) {
    __shared__ float tile[32][33];
    int b = blockIdx.z;
    int s0 = blockIdx.x * 32, c0 = blockIdx.y * 32;
    int tx = threadIdx.x, ty = threadIdx.y;
    const float* xp = x + (size_t)b * PER_B;
#pragma unroll
    for (int i = 0; i < 4; i++) {
        int c = c0 + ty + i*8;
        tile[ty + i*8][tx] = xp[(size_t)c*SS + s0 + tx];
    }
    __syncthreads();
    float mean = g_stats[2*b], inv = g_stats[2*b+1];
    int c = c0 + tx;
    float w  = gw[c] * inv;
    float bias = gb[c] - mean * w;
#pragma unroll
    for (int i = 0; i < 4; i++) {
        int s = s0 + ty + i*8;
        float v = tile[tx][ty + i*8] * w + bias;
        g_h2[((size_t)b*SS + s) * 512 + c] = __float2half_rn(v);
    }
}

// ---------------- HMMA GEMM (R10 config): 128x128 CTA, 8 warps, BK=32, 4-stage ----------------
// EPI: 0 = QKV out (Q scaled, K direct, V staged transpose), 3 = proj^T +bias+resid
#define STAGE_BYTES 20480
#define DYN_SMEM 81920

__device__ __forceinline__ void prefetch_tile(char* smem, int stage,
    const f16* __restrict__ A, int lda, const f16* __restrict__ B, int ldb,
    int m0, int n0, int k0, int tid)
{
    char* as = smem + stage*STAGE_BYTES;
    char* bs = as + 10240;
    int row = tid >> 1, seg = tid & 1;
    const f16* ag = A + (size_t)(m0 + row)*lda + k0 + seg*16;
    const f16* bg = B + (size_t)(n0 + row)*ldb + k0 + seg*16;
    uint32_t asw = smem_u32(as + row*80 + seg*32);
    uint32_t bsw = smem_u32(bs + row*80 + seg*32);
    CP_ASYNC16(asw,      (const void*)ag);
    CP_ASYNC16(asw + 16, (const void*)(ag + 8));
    CP_ASYNC16(bsw,      (const void*)bg);
    CP_ASYNC16(bsw + 16, (const void*)(bg + 8));
}

template<int EPI>
__global__ __launch_bounds__(256, 2)
void mm_gemm(const f16* __restrict__ A, int lda, long long sA,
             const f16* __restrict__ B, int ldb, long long sB,
             float* __restrict__ Out,
             const float* __restrict__ bias,
             const float* __restrict__ resid,
             float scale, int K)
{
    extern __shared__ char smem[];
    int tid = threadIdx.x, lane = tid & 31, wid = tid >> 5;
    int wm = wid >> 1, wn = wid & 1;
    int z = blockIdx.z;
    int m0 = blockIdx.y * 128, n0 = blockIdx.x * 128;
    A += (size_t)z * sA;
    B += (size_t)z * sB;

    float acc[2][8][4];
#pragma unroll
    for (int i = 0; i < 2; i++)
#pragma unroll
        for (int j = 0; j < 8; j++)
#pragma unroll
            for (int r = 0; r < 4; r++) acc[i][j][r] = 0.f;

    uint32_t a_off = (uint32_t)((wm*32 + (lane & 15)) * 80 + (lane >> 4) * 16);
    uint32_t b_off = (uint32_t)((wn*64 + (lane & 7) + ((lane >> 4) << 3)) * 80
                                + ((lane >> 3) & 1) * 16);
    uint32_t smem_base = smem_u32(smem);

    int nch = K >> 5;
#pragma unroll
    for (int p = 0; p < 3; p++) {
        if (p < nch) { prefetch_tile(smem, p, A, lda, B, ldb, m0, n0, p*32, tid); CP_COMMIT(); }
    }

    int st = 0;
    for (int c = 0; c < nch; c++) {
        int rem = nch - 1 - c;
        if (rem >= 2) CP_WAIT2(); else if (rem == 1) CP_WAIT1(); else CP_WAIT0();
        __syncthreads();
        if (c + 3 < nch) {
            prefetch_tile(smem, (st + 3) & 3, A, lda, B, ldb, m0, n0, (c+3)*32, tid);
            CP_COMMIT();
        }

        uint32_t as_b = smem_base + st*STAGE_BYTES + a_off;
        uint32_t bs_b = smem_base + st*STAGE_BYTES + 10240 + b_off;
#pragma unroll
        for (int ks = 0; ks < 2; ks++) {
            uint32_t a[2][4], b[4][4];
#pragma unroll
            for (int mf = 0; mf < 2; mf++)
                LDM_X4(a[mf][0], a[mf][1], a[mf][2], a[mf][3], as_b + mf*1280 + ks*32);
#pragma unroll
            for (int nf2 = 0; nf2 < 4; nf2++)
                LDM_X4(b[nf2][0], b[nf2][1], b[nf2][2], b[nf2][3], bs_b + nf2*1280 + ks*32);
#pragma unroll
            for (int mf = 0; mf < 2; mf++)
#pragma unroll
                for (int nf = 0; nf < 8; nf++)
                    MMA16816(acc[mf][nf], a[mf], b[nf>>1][(nf&1)*2], b[nf>>1][(nf&1)*2+1]);
        }
        st = (st + 1) & 3;
    }

    int r4 = lane >> 2, cp = (lane & 3) * 2;

    if constexpr (EPI == 0) {
        if (n0 < 1024) {             // Q (scaled) / K direct half2 stores
            f16* dst = (n0 < 512) ? g_q2 : g_k2;
            int nbase = (n0 < 512) ? n0 : (n0 - 512);
            float sc = (n0 < 512) ? scale : 1.f;
#pragma unroll
            for (int mf = 0; mf < 2; mf++)
#pragma unroll
                for (int nf = 0; nf < 8; nf++) {
                    int rr = m0 + wm*32 + mf*16 + r4;
                    int cc = wn*64 + nf*8 + cp;
                    float b0 = bias[n0 + cc], b1 = bias[n0 + cc + 1];
                    *(__half2*)&dst[(size_t)rr * 512 + nbase + cc] =
                        __floats2half2_rn((acc[mf][nf][0] + b0)*sc, (acc[mf][nf][1] + b1)*sc);
                    *(__half2*)&dst[(size_t)(rr + 8) * 512 + nbase + cc] =
                        __floats2half2_rn((acc[mf][nf][2] + b0)*sc, (acc[mf][nf][3] + b1)*sc);
                }
        } else {                     // V: staged transpose -> [B,C,S]
            __syncthreads();
            float* tile = (float*)smem;
#pragma unroll
            for (int mf = 0; mf < 2; mf++)
#pragma unroll
                for (int nf = 0; nf < 8; nf++) {
                    int rr = wm*32 + mf*16 + r4, cc = wn*64 + nf*8 + cp;
                    tile[rr*132 + cc]       = acc[mf][nf][0];
                    tile[rr*132 + cc + 1]   = acc[mf][nf][1];
                    tile[(rr+8)*132 + cc]   = acc[mf][nf][2];
                    tile[(rr+8)*132 + cc+1] = acc[mf][nf][3];
                }
            __syncthreads();
            for (int idx = tid; idx < 16384; idx += 256) {
                int rt = idx & 127, ct = idx >> 7;
                float v = tile[rt*132 + ct] + bias[n0 + ct];
                int m = m0 + rt, b = m >> 10, s = m & 1023;
                int cg = n0 + ct - 1024;
                g_v2[((size_t)b*512 + cg) * 1024 + s] = __float2half_rn(v);
            }
        }
    } else {                         // proj^T: m=c-dim, n=global s; +bias+resid
#pragma unroll
        for (int mf = 0; mf < 2; mf++) {
            int rr = m0 + wm*32 + mf*16 + r4;
            float bias_r  = bias[rr], bias_r8 = bias[rr + 8];
#pragma unroll
            for (int nf = 0; nf < 8; nf++) {
                int n = n0 + wn*64 + nf*8 + cp;
                int b = n >> 10, s = n & 1023;
                size_t o0 = ((size_t)b * 512 + rr) * 1024 + s;
                size_t o1 = ((size_t)b * 512 + rr + 8) * 1024 + s;
                float2 rv0 = *(const float2*)&resid[o0];
                float2 rv1 = *(const float2*)&resid[o1];
                float2 w0 = {acc[mf][nf][0] + bias_r  + rv0.x, acc[mf][nf][1] + bias_r  + rv0.y};
                float2 w1 = {acc[mf][nf][2] + bias_r8 + rv1.x, acc[mf][nf][3] + bias_r8 + rv1.y};
                *(float2*)&Out[o0] = w0;
                *(float2*)&Out[o1] = w1;
            }
        }
    }
}

// ---------------- fused flash attention: scores + softmax + AV ----------------
// CTA: 32 q-rows, 256 threads, 8 warps (wm in 0..1 rows16, wn in 0..3).
// Phase A: S(32x128) = Q.K^T over c=512 (16 chunks of 32, 3-stage QK).
// Softmax: online, quad-shfl + smem cross-warp reduce.
// Phase B: O(32x512) += P.V over 128 keys (8 chunks of 16, 3-stage V).
// smem: QK stages 3*12800=38400 (P 8704 + red 1024 overlap dead stage0);
//       V stages at 38400: 3*24576=73728; total 112128.
#define AT_QK_STG 12800
#define AT_V_OFF  38400
#define AT_V_STG  24576
#define AT_RMAX   8704
#define AT_RSUM   9216
#define AT_SMEM   112128

__global__ __launch_bounds__(256, 2)
void fused_attn()
{
    extern __shared__ char smem[];
    uint32_t sb = smem_u32(smem);
    int tid = threadIdx.x, lane = tid & 31, wid = tid >> 5;
    int wm = wid >> 2, wn = wid & 3;
    int b = blockIdx.y, q0 = blockIdx.x * 32;
    const f16* Qp = g_q2 + ((size_t)b*1024 + q0) * 512;
    const f16* Kp = g_k2 + (size_t)b*1024*512;
    const f16* Vp = g_v2 + (size_t)b*512*1024;

    int r4 = lane >> 2, cp = (lane & 3) * 2;

    float accO[16][4];
#pragma unroll
    for (int i = 0; i < 16; i++)
#pragma unroll
        for (int j = 0; j < 4; j++) accO[i][j] = 0.f;
    float m_run0 = -1e30f, m_run1 = -1e30f, l_run0 = 0.f, l_run1 = 0.f;

    uint32_t aQ = (uint32_t)((wm*16 + (lane & 15)) * 80 + (lane >> 4) * 16);
    uint32_t bK = (uint32_t)(2560 + (wn*32 + (lane & 7) + ((lane >> 4) << 3)) * 80
                             + ((lane >> 3) & 1) * 16);
    uint32_t aP = (uint32_t)((wm*16 + (lane & 15)) * 272 + (lane >> 4) * 16);
    uint32_t bV = (uint32_t)((wn*128 + (lane & 7) + ((lane >> 4) << 3)) * 48
                             + ((lane >> 3) & 1) * 16);
    float* rmax = (float*)(smem + AT_RMAX);
    float* rsum = (float*)(smem + AT_RSUM);
    f16*   Psm  = (f16*)smem;
    int rowA = wm*16 + r4, rowB = rowA + 8;

    for (int kb = 0; kb < 8; kb++) {
        const f16* Kb = Kp + (size_t)kb*128*512;

        // ---- phase A: S = Q.K^T (16 c-chunks, 3-stage) ----
        float accS[4][4];
#pragma unroll
        for (int i = 0; i < 4; i++)
#pragma unroll
            for (int j = 0; j < 4; j++) accS[i][j] = 0.f;

        {
            // prefetch helper inline: chunk c0 into stage s
            auto pf = [&](int s, int c0) {
                char* base = smem + s*AT_QK_STG;
#pragma unroll
                for (int i = 0; i < 2; i++) {          // K: 512 tasks
                    int task = tid + i*256, row = task >> 2, seg = task & 3;
                    CP_ASYNC16(smem_u32(base + 2560 + row*80 + seg*16),
                               (const void*)(Kb + (size_t)row*512 + c0 + seg*8));
                }
                if (tid < 128) {                        // Q: 128 tasks
                    int row = tid >> 2, seg = tid & 3;
                    CP_ASYNC16(smem_u32(base + row*80 + seg*16),
                               (const void*)(Qp + (size_t)row*512 + c0 + seg*8));
                }
            };
            pf(0, 0);  CP_COMMIT();
            pf(1, 32); CP_COMMIT();
            int st = 0;
            for (int c = 0; c < 16; c++) {
                if (c + 2 <= 16) CP_WAIT1(); else CP_WAIT0();
                __syncthreads();
                if (c + 2 < 16) {
                    int ns = st + 2; if (ns >= 3) ns -= 3;
                    pf(ns, (c+2)*32); CP_COMMIT();
                }
                uint32_t qb = sb + st*AT_QK_STG + aQ;
                uint32_t kbm = sb + st*AT_QK_STG + bK;
#pragma unroll
                for (int ks = 0; ks < 2; ks++) {
                    uint32_t a[4], bf[2][4];
                    LDM_X4(a[0], a[1], a[2], a[3], qb + ks*32);
#pragma unroll
                    for (int nf2 = 0; nf2 < 2; nf2++)
                        LDM_X4(bf[nf2][0], bf[nf2][1], bf[nf2][2], bf[nf2][3],
                               kbm + nf2*1280 + ks*32);
#pragma unroll
                    for (int nf = 0; nf < 4; nf++)
                        MMA16816(accS[nf], a, bf[nf>>1][(nf&1)*2], bf[nf>>1][(nf&1)*2+1]);
                }
                st++; if (st == 3) st = 0;
            }
        }
        __syncthreads();   // all warps done reading QK stages (P overlaps stage0)

        // ---- prefetch V chunks 0,1 (overlap with softmax) ----
        auto pfv = [&](int s, int ch) {
            char* base = smem + AT_V_OFF + s*AT_V_STG;
#pragma unroll
            for (int i = 0; i < 4; i++) {
                int task = tid + i*256, row = task >> 1, seg = task & 1;
                CP_ASYNC16(smem_u32(base + row*48 + seg*16),
                           (const void*)(Vp + (size_t)row*1024 + kb*128 + ch*16 + seg*8));
            }
        };
        pfv(0, 0); CP_COMMIT();
        pfv(1, 1); CP_COMMIT();

        // ---- softmax (online) ----
        float m0 = -1e30f, m1 = -1e30f;
#pragma unroll
        for (int nf = 0; nf < 4; nf++) {
            m0 = fmaxf(m0, fmaxf(accS[nf][0], accS[nf][1]));
            m1 = fmaxf(m1, fmaxf(accS[nf][2], accS[nf][3]));
        }
        m0 = fmaxf(m0, __shfl_xor_sync(0xffffffffu, m0, 1));
        m0 = fmaxf(m0, __shfl_xor_sync(0xffffffffu, m0, 2));
        m1 = fmaxf(m1, __shfl_xor_sync(0xffffffffu, m1, 1));
        m1 = fmaxf(m1, __shfl_xor_sync(0xffffffffu, m1, 2));
        if ((lane & 3) == 0) { rmax[rowA*4 + wn] = m0; rmax[rowB*4 + wn] = m1; }
        __syncthreads();
        float mb0 = fmaxf(fmaxf(rmax[rowA*4+0], rmax[rowA*4+1]),
                          fmaxf(rmax[rowA*4+2], rmax[rowA*4+3]));
        float mb1 = fmaxf(fmaxf(rmax[rowB*4+0], rmax[rowB*4+1]),
                          fmaxf(rmax[rowB*4+2], rmax[rowB*4+3]));
        float mn0 = fmaxf(m_run0, mb0), mn1 = fmaxf(m_run1, mb1);
        float sc0 = __expf(m_run0 - mn0), sc1 = __expf(m_run1 - mn1);
        float s0 = 0.f, s1 = 0.f;
#pragma unroll
        for (int nf = 0; nf < 4; nf++) {
            float p0 = __expf(accS[nf][0] - mn0);
            float p1 = __expf(accS[nf][1] - mn0);
            float p2 = __expf(accS[nf][2] - mn1);
            float p3 = __expf(accS[nf][3] - mn1);
            s0 += p0 + p1; s1 += p2 + p3;
            int key = wn*32 + nf*8 + cp;
            *(__half2*)&Psm[rowA*136 + key] = __floats2half2_rn(p0, p1);
            *(__half2*)&Psm[rowB*136 + key] = __floats2half2_rn(p2, p3);
        }
        s0 += __shfl_xor_sync(0xffffffffu, s0, 1);
        s0 += __shfl_xor_sync(0xffffffffu, s0, 2);
        s1 += __shfl_xor_sync(0xffffffffu, s1, 1);
        s1 += __shfl_xor_sync(0xffffffffu, s1, 2);
        if ((lane & 3) == 0) { rsum[rowA*4 + wn] = s0; rsum[rowB*4 + wn] = s1; }
        __syncthreads();   // rsum + P visible
        float lb0 = (rsum[rowA*4+0] + rsum[rowA*4+1]) + (rsum[rowA*4+2] + rsum[rowA*4+3]);
        float lb1 = (rsum[rowB*4+0] + rsum[rowB*4+1]) + (rsum[rowB*4+2] + rsum[rowB*4+3]);
        l_run0 = l_run0 * sc0 + lb0; l_run1 = l_run1 * sc1 + lb1;
        m_run0 = mn0; m_run1 = mn1;
#pragma unroll
        for (int i = 0; i < 16; i++) {
            accO[i][0] *= sc0; accO[i][1] *= sc0;
            accO[i][2] *= sc1; accO[i][3] *= sc1;
        }

        // ---- phase B: O += P.V (8 key-chunks of 16, 3-stage V) ----
        {
            int vst = 0;
            for (int ch = 0; ch < 8; ch++) {
                if (ch + 2 <= 8) CP_WAIT1(); else CP_WAIT0();
                __syncthreads();
                if (ch + 2 < 8) {
                    int ns = vst + 2; if (ns >= 3) ns -= 3;
                    pfv(ns, ch + 2); CP_COMMIT();
                }
                uint32_t a[4];
                LDM_X4(a[0], a[1], a[2], a[3], sb + aP + ch*32);
                uint32_t vb = sb + AT_V_OFF + vst*AT_V_STG + bV;
#pragma unroll
                for (int nf2 = 0; nf2 < 8; nf2++) {
                    uint32_t bf[4];
                    LDM_X4(bf[0], bf[1], bf[2], bf[3], vb + nf2*768);
                    MMA16816(accO[nf2*2],     a, bf[0], bf[1]);
                    MMA16816(accO[nf2*2 + 1], a, bf[2], bf[3]);
                }
                vst++; if (vst == 3) vst = 0;
            }
        }
        __syncthreads();   // P/stages dead before next key-block prefetch
    }

    // ---- epilogue: O /= l, write ao2 ----
    float rl0 = 1.f / l_run0, rl1 = 1.f / l_run1;
    int gr0 = b*1024 + q0 + rowA, gr1 = b*1024 + q0 + rowB;
#pragma unroll
    for (int nf = 0; nf < 16; nf++) {
        int cc = wn*128 + nf*8 + cp;
        *(__half2*)&g_ao2[(size_t)gr0 * 512 + cc] =
            __floats2half2_rn(accO[nf][0] * rl0, accO[nf][1] * rl0);
        *(__half2*)&g_ao2[(size_t)gr1 * 512 + cc] =
            __floats2half2_rn(accO[nf][2] * rl1, accO[nf][3] * rl1);
    }
}

// ---------------- launch ----------------
extern "C" void kernel_launch(void* const* d_in, const int* in_sizes, int n_in,
                              void* d_out, int out_size) {
    const float* x      = (const float*)d_in[0];
    const float* gn_w   = (const float*)d_in[1];
    const float* gn_b   = (const float*)d_in[2];
    const float* qkv_w  = (const float*)d_in[3];
    const float* qkv_b  = (const float*)d_in[4];
    const float* proj_w = (const float*)d_in[5];
    const float* proj_b = (const float*)d_in[6];
    float* out = (float*)d_out;

    cudaFuncSetAttribute(mm_gemm<0>, cudaFuncAttributeMaxDynamicSharedMemorySize, DYN_SMEM);
    cudaFuncSetAttribute(mm_gemm<3>, cudaFuncAttributeMaxDynamicSharedMemorySize, DYN_SMEM);
    cudaFuncSetAttribute(fused_attn, cudaFuncAttributeMaxDynamicSharedMemorySize, AT_SMEM);

    f16 *h2, *w1, *w2, *ao2;
    cudaGetSymbolAddress((void**)&h2,  g_h2);
    cudaGetSymbolAddress((void**)&w1,  g_w1);
    cudaGetSymbolAddress((void**)&w2,  g_w2);
    cudaGetSymbolAddress((void**)&ao2, g_ao2);

    // 1. weight convert
    wconv<<<(2048*512 + 255)/256, 256>>>(qkv_w, proj_w);

    // 2. fused GroupNorm stats
    gn_stats<<<dim3(64, BB), 256>>>(x);

    // 3. normalize + transpose (fp16)
    norm_split<<<dim3(SS/32, CC/32, BB), dim3(32, 8)>>>(x, gn_w, gn_b);

    // 4. QKV GEMM: M=16384, N=1536, K=512 (Q prescaled)  <-- profiled slot
    mm_gemm<0><<<dim3(12, 128, 1), 256, DYN_SMEM>>>(
        h2, 512, 0LL, w1, 512, 0LL,
        nullptr, qkv_b, nullptr, 0.044194173824159216f, 512);

    // 5. fused attention: scores + softmax + AV
    fused_attn<<<dim3(32, BB), 256, AT_SMEM>>>();

    // 6. proj^T + bias + residual -> NCHW out
    mm_gemm<3><<<dim3(128, 4, 1), 256, DYN_SMEM>>>(
        w2, 512, 0LL, ao2, 512, 0LL, out, proj_b, x, 1.f, 512);
}

// round 13
// speedup vs baseline: 1.2496x; 1.2496x over previous
#include <cuda_runtime.h>
#include <cuda_fp16.h>
#include <cstdint>
#include <math.h>

#define BB 16
#define CC 512
#define SS 1024
#define PER_B (CC*SS)

typedef __half f16;

// ---------------- scratch (__device__ globals; no allocs) ----------------
__device__ float g_psum[BB*64], g_psq[BB*64], g_stats[BB*2];
__device__ unsigned g_ctr;
__device__ f16  g_h2 [(size_t)BB*SS*512];    // norm'd [B*S, C] fp16 (A-side)
__device__ f16  g_w1 [1536*512];             // qkv_w fp16 (B-side)
__device__ f16  g_w2 [512*512];              // proj_w fp16 (A-side for proj)
__device__ f16  g_q2 [(size_t)BB*SS*512];    // Q*scale fp16 (A-side)
__device__ f16  g_k2 [(size_t)BB*SS*512];    // K fp16 (B-side)
__device__ f16  g_v2 [(size_t)BB*CC*1024];   // V transposed [B,C,S] fp16 (B-side)
__device__ f16  g_p2 [(size_t)BB*SS*1024];   // probs [B*S, S] fp16 (A-side)
__device__ f16  g_ao2[(size_t)BB*SS*512];    // attn out fp16 (B-side for proj)
__device__ float g_sc [(size_t)BB*SS*SS];    // scores fp32

// ---------------- helpers ----------------
__device__ __forceinline__ uint32_t smem_u32(const void* p) {
    uint32_t a;
    asm("{ .reg .u64 t; cvta.to.shared.u64 t, %1; cvt.u32.u64 %0, t; }" : "=r"(a) : "l"(p));
    return a;
}
#define CP_ASYNC16(dst, src) \
    asm volatile("cp.async.cg.shared.global [%0], [%1], 16;" :: "r"(dst), "l"(src) : "memory")
#define CP_COMMIT() asm volatile("cp.async.commit_group;" ::: "memory")
#define CP_WAIT0()  asm volatile("cp.async.wait_group 0;" ::: "memory")
#define CP_WAIT1()  asm volatile("cp.async.wait_group 1;" ::: "memory")
#define CP_WAIT2()  asm volatile("cp.async.wait_group 2;" ::: "memory")
#define LDM_X4(r0,r1,r2,r3,addr) \
    asm volatile("ldmatrix.sync.aligned.m8n8.x4.shared.b16 {%0,%1,%2,%3}, [%4];" \
        : "=r"(r0),"=r"(r1),"=r"(r2),"=r"(r3) : "r"(addr))
// f16-accumulate MMA: d0 packs (c0,c1) for row r; d1 packs (c2,c3) for row r+8
#define MMA16816H(d, a, b0, b1) \
    asm volatile("mma.sync.aligned.m16n8k16.row.col.f16.f16.f16.f16 " \
        "{%0,%1}, {%2,%3,%4,%5}, {%6,%7}, {%0,%1};" \
        : "+r"((d)[0]), "+r"((d)[1]) \
        : "r"((a)[0]), "r"((a)[1]), "r"((a)[2]), "r"((a)[3]), "r"(b0), "r"(b1))

// ---------------- weight convert (plain fp16) ----------------
__global__ void wconv(const float* __restrict__ w1s, const float* __restrict__ w2s) {
    int i = blockIdx.x * 256 + threadIdx.x;
    if (i < 2048*512) {
        if (i < 1536*512) g_w1[i] = __float2half_rn(w1s[i]);
        else              g_w2[i - 1536*512] = __float2half_rn(w2s[i - 1536*512]);
    }
}

// ---------------- fused GroupNorm stats ----------------
__global__ void gn_stats(const float* __restrict__ x) {
    int b = blockIdx.y, chunk = blockIdx.x, t = threadIdx.x;
    const float* p = x + (size_t)b*PER_B + (size_t)chunk*8192;
    float s = 0.f, q = 0.f;
#pragma unroll
    for (int i = 0; i < 32; i++) { float v = p[t + i*256]; s += v; q += v*v; }
    __shared__ float ss_[8], sq_[8];
    for (int o = 16; o > 0; o >>= 1) {
        s += __shfl_down_sync(0xffffffffu, s, o);
        q += __shfl_down_sync(0xffffffffu, q, o);
    }
    if ((t & 31) == 0) { ss_[t >> 5] = s; sq_[t >> 5] = q; }
    __syncthreads();
    __shared__ int isLast;
    if (t == 0) {
        float S2 = 0.f, Q2 = 0.f;
#pragma unroll
        for (int i = 0; i < 8; i++) { S2 += ss_[i]; Q2 += sq_[i]; }
        g_psum[b*64 + chunk] = S2; g_psq[b*64 + chunk] = Q2;
        __threadfence();
        unsigned v = atomicAdd(&g_ctr, 1u);
        isLast = (v == 64u*BB - 1u);
    }
    __syncthreads();
    if (isLast) {
        if (t < BB) {
            float s2 = 0.f, q2 = 0.f;
            for (int i = 0; i < 64; i++) { s2 += g_psum[t*64+i]; q2 += g_psq[t*64+i]; }
            float mean = s2 * (1.f/(float)PER_B);
            float var  = q2 * (1.f/(float)PER_B) - mean*mean;
            g_stats[2*t] = mean; g_stats[2*t+1] = rsqrtf(var + 1e-5f);
        }
        if (t == 0) g_ctr = 0u;
    }
}

// ---------------- normalize + transpose -> g_h2 [B*S, C] fp16 ----------------
__global__ void norm_split(const float* __restrict__ x,
                           const float* __restrict__ gw,
                           const float* __restrict__ gb) {
    __shared__ float tile[32][33];
    int b = blockIdx.z;
    int s0 = blockIdx.x * 32, c0 = blockIdx.y * 32;
    int tx = threadIdx.x, ty = threadIdx.y;
    const float* xp = x + (size_t)b * PER_B;
#pragma unroll
    for (int i = 0; i < 4; i++) {
        int c = c0 + ty + i*8;
        tile[ty + i*8][tx] = xp[(size_t)c*SS + s0 + tx];
    }
    __syncthreads();
    float mean = g_stats[2*b], inv = g_stats[2*b+1];
    int c = c0 + tx;
    float w  = gw[c] * inv;
    float bias = gb[c] - mean * w;
#pragma unroll
    for (int i = 0; i < 4; i++) {
        int s = s0 + ty + i*8;
        float v = tile[tx][ty + i*8] * w + bias;
        g_h2[((size_t)b*SS + s) * 512 + c] = __float2half_rn(v);
    }
}

// ---------------- HMMA GEMM (f16 accum): 128x128 CTA, 8 warps, BK=32, 4-stage ----------------
// NT: out[m,n] = sum_k A[m,k]*B[n,k]
// EPI: 0 = QKV out (Q scaled, K direct, V staged transpose), 1 = scores (raw, Q prescaled),
//      2 = AV out, 3 = proj^T +bias+resid
#define STAGE_BYTES 20480
#define DYN_SMEM 81920

__device__ __forceinline__ void prefetch_tile(char* smem, int stage,
    const f16* __restrict__ A, int lda, const f16* __restrict__ B, int ldb,
    int m0, int n0, int k0, int tid)
{
    char* as = smem + stage*STAGE_BYTES;
    char* bs = as + 10240;
    int row = tid >> 1, seg = tid & 1;
    const f16* ag = A + (size_t)(m0 + row)*lda + k0 + seg*16;
    const f16* bg = B + (size_t)(n0 + row)*ldb + k0 + seg*16;
    uint32_t asw = smem_u32(as + row*80 + seg*32);
    uint32_t bsw = smem_u32(bs + row*80 + seg*32);
    CP_ASYNC16(asw,      (const void*)ag);
    CP_ASYNC16(asw + 16, (const void*)(ag + 8));
    CP_ASYNC16(bsw,      (const void*)bg);
    CP_ASYNC16(bsw + 16, (const void*)(bg + 8));
}

template<int EPI>
__global__ __launch_bounds__(256, 2)
void mm_gemm(const f16* __restrict__ A, int lda, long long sA,
             const f16* __restrict__ B, int ldb, long long sB,
             float* __restrict__ Out,
             const float* __restrict__ bias,
             const float* __restrict__ resid,
             float scale, int K)
{
    extern __shared__ char smem[];
    int tid = threadIdx.x, lane = tid & 31, wid = tid >> 5;
    int wm = wid >> 1, wn = wid & 1;
    int z = blockIdx.z;
    int m0 = blockIdx.y * 128, n0 = blockIdx.x * 128;
    A += (size_t)z * sA;
    B += (size_t)z * sB;

    uint32_t acc[2][8][2];
#pragma unroll
    for (int i = 0; i < 2; i++)
#pragma unroll
        for (int j = 0; j < 8; j++) { acc[i][j][0] = 0u; acc[i][j][1] = 0u; }

    uint32_t a_off = (uint32_t)((wm*32 + (lane & 15)) * 80 + (lane >> 4) * 16);
    uint32_t b_off = (uint32_t)((wn*64 + (lane & 7) + ((lane >> 4) << 3)) * 80
                                + ((lane >> 3) & 1) * 16);
    uint32_t smem_base = smem_u32(smem);

    int nch = K >> 5;
#pragma unroll
    for (int p = 0; p < 3; p++) {
        if (p < nch) { prefetch_tile(smem, p, A, lda, B, ldb, m0, n0, p*32, tid); CP_COMMIT(); }
    }

    int st = 0;
    for (int c = 0; c < nch; c++) {
        int rem = nch - 1 - c;
        if (rem >= 2) CP_WAIT2(); else if (rem == 1) CP_WAIT1(); else CP_WAIT0();
        __syncthreads();
        if (c + 3 < nch) {
            prefetch_tile(smem, (st + 3) & 3, A, lda, B, ldb, m0, n0, (c+3)*32, tid);
            CP_COMMIT();
        }

        uint32_t as_b = smem_base + st*STAGE_BYTES + a_off;
        uint32_t bs_b = smem_base + st*STAGE_BYTES + 10240 + b_off;
#pragma unroll
        for (int ks = 0; ks < 2; ks++) {
            uint32_t a[2][4], b[4][4];
#pragma unroll
            for (int mf = 0; mf < 2; mf++)
                LDM_X4(a[mf][0], a[mf][1], a[mf][2], a[mf][3], as_b + mf*1280 + ks*32);
#pragma unroll
            for (int nf2 = 0; nf2 < 4; nf2++)
                LDM_X4(b[nf2][0], b[nf2][1], b[nf2][2], b[nf2][3], bs_b + nf2*1280 + ks*32);
#pragma unroll
            for (int mf = 0; mf < 2; mf++)
#pragma unroll
                for (int nf = 0; nf < 8; nf++)
                    MMA16816H(acc[mf][nf], a[mf], b[nf>>1][(nf&1)*2], b[nf>>1][(nf&1)*2+1]);
        }
        st = (st + 1) & 3;
    }

    int r4 = lane >> 2, cp = (lane & 3) * 2;

    if constexpr (EPI == 0) {
        if (n0 < 1024) {             // Q (scaled) / K direct half2 stores
            f16* dst = (n0 < 512) ? g_q2 : g_k2;
            int nbase = (n0 < 512) ? n0 : (n0 - 512);
            float sc = (n0 < 512) ? scale : 1.f;
#pragma unroll
            for (int mf = 0; mf < 2; mf++)
#pragma unroll
                for (int nf = 0; nf < 8; nf++) {
                    int rr = m0 + wm*32 + mf*16 + r4;
                    int cc = wn*64 + nf*8 + cp;
                    float b0 = bias[n0 + cc], b1 = bias[n0 + cc + 1];
                    float2 v0 = __half22float2(*(__half2*)&acc[mf][nf][0]);
                    float2 v1 = __half22float2(*(__half2*)&acc[mf][nf][1]);
                    *(__half2*)&dst[(size_t)rr * 512 + nbase + cc] =
                        __floats2half2_rn((v0.x + b0)*sc, (v0.y + b1)*sc);
                    *(__half2*)&dst[(size_t)(rr + 8) * 512 + nbase + cc] =
                        __floats2half2_rn((v1.x + b0)*sc, (v1.y + b1)*sc);
                }
        } else {                     // V: staged transpose -> [B,C,S]
            __syncthreads();
            float* tile = (float*)smem;
#pragma unroll
            for (int mf = 0; mf < 2; mf++)
#pragma unroll
                for (int nf = 0; nf < 8; nf++) {
                    int rr = wm*32 + mf*16 + r4, cc = wn*64 + nf*8 + cp;
                    float2 v0 = __half22float2(*(__half2*)&acc[mf][nf][0]);
                    float2 v1 = __half22float2(*(__half2*)&acc[mf][nf][1]);
                    tile[rr*132 + cc]       = v0.x;
                    tile[rr*132 + cc + 1]   = v0.y;
                    tile[(rr+8)*132 + cc]   = v1.x;
                    tile[(rr+8)*132 + cc+1] = v1.y;
                }
            __syncthreads();
            for (int idx = tid; idx < 16384; idx += 256) {
                int rt = idx & 127, ct = idx >> 7;
                float v = tile[rt*132 + ct] + bias[n0 + ct];
                int m = m0 + rt, b = m >> 10, s = m & 1023;
                int cg = n0 + ct - 1024;
                g_v2[((size_t)b*512 + cg) * 1024 + s] = __float2half_rn(v);
            }
        }
    } else if constexpr (EPI == 1) { // scores fp32 (Q prescaled, raw store)
        float* op = Out + (size_t)z * SS * SS;
#pragma unroll
        for (int mf = 0; mf < 2; mf++)
#pragma unroll
            for (int nf = 0; nf < 8; nf++) {
                int rr = m0 + wm*32 + mf*16 + r4;
                int cc = n0 + wn*64 + nf*8 + cp;
                float2 v0 = __half22float2(*(__half2*)&acc[mf][nf][0]);
                float2 v1 = __half22float2(*(__half2*)&acc[mf][nf][1]);
                *(float2*)&op[(size_t)rr * SS + cc] = v0;
                *(float2*)&op[(size_t)(rr + 8) * SS + cc] = v1;
            }
    } else if constexpr (EPI == 2) { // AV: raw packed half2 stores
#pragma unroll
        for (int mf = 0; mf < 2; mf++)
#pragma unroll
            for (int nf = 0; nf < 8; nf++) {
                int rr = m0 + wm*32 + mf*16 + r4;
                int cc = n0 + wn*64 + nf*8 + cp;
                *(uint32_t*)&g_ao2[((size_t)z * SS + rr) * 512 + cc] = acc[mf][nf][0];
                *(uint32_t*)&g_ao2[((size_t)z * SS + rr + 8) * 512 + cc] = acc[mf][nf][1];
            }
    } else {                         // proj^T: m=c-dim, n=global s; +bias+resid
#pragma unroll
        for (int mf = 0; mf < 2; mf++) {
            int rr = m0 + wm*32 + mf*16 + r4;
            float bias_r  = bias[rr], bias_r8 = bias[rr + 8];
#pragma unroll
            for (int nf = 0; nf < 8; nf++) {
                int n = n0 + wn*64 + nf*8 + cp;
                int b = n >> 10, s = n & 1023;
                size_t o0 = ((size_t)b * 512 + rr) * 1024 + s;
                size_t o1 = ((size_t)b * 512 + rr + 8) * 1024 + s;
                float2 rv0 = *(const float2*)&resid[o0];
                float2 rv1 = *(const float2*)&resid[o1];
                float2 v0 = __half22float2(*(__half2*)&acc[mf][nf][0]);
                float2 v1 = __half22float2(*(__half2*)&acc[mf][nf][1]);
                float2 w0 = {v0.x + bias_r  + rv0.x, v0.y + bias_r  + rv0.y};
                float2 w1 = {v1.x + bias_r8 + rv1.x, v1.y + bias_r8 + rv1.y};
                *(float2*)&Out[o0] = w0;
                *(float2*)&Out[o1] = w1;
            }
        }
    }
}

// ---------------- softmax over 1024-wide rows, plain fp16 output ----------------
__global__ void softmax_rows(const float* __restrict__ sc) {
    const float* row = sc + (size_t)blockIdx.x * SS;
    f16* orow = g_p2 + (size_t)blockIdx.x * 1024;
    int t = threadIdx.x;
    float v[4];
#pragma unroll
    for (int i = 0; i < 4; i++) v[i] = row[t + i*256];
    float m = fmaxf(fmaxf(v[0], v[1]), fmaxf(v[2], v[3]));
    __shared__ float red[8];
    for (int o = 16; o > 0; o >>= 1) m = fmaxf(m, __shfl_xor_sync(0xffffffffu, m, o));
    if ((t & 31) == 0) red[t >> 5] = m;
    __syncthreads();
    float mm = fmaxf(fmaxf(fmaxf(red[0], red[1]), fmaxf(red[2], red[3])),
                     fmaxf(fmaxf(red[4], red[5]), fmaxf(red[6], red[7])));
    float s = 0.f;
#pragma unroll
    for (int i = 0; i < 4; i++) { v[i] = __expf(v[i] - mm); s += v[i]; }
    for (int o = 16; o > 0; o >>= 1) s += __shfl_xor_sync(0xffffffffu, s, o);
    __syncthreads();
    if ((t & 31) == 0) red[t >> 5] = s;
    __syncthreads();
    float tot = ((red[0]+red[1]) + (red[2]+red[3])) + ((red[4]+red[5]) + (red[6]+red[7]));
    float invs = 1.f / tot;
#pragma unroll
    for (int i = 0; i < 4; i++)
        orow[t + i*256] = __float2half_rn(v[i] * invs);
}

// ---------------- launch ----------------
extern "C" void kernel_launch(void* const* d_in, const int* in_sizes, int n_in,
                              void* d_out, int out_size) {
    const float* x      = (const float*)d_in[0];
    const float* gn_w   = (const float*)d_in[1];
    const float* gn_b   = (const float*)d_in[2];
    const float* qkv_w  = (const float*)d_in[3];
    const float* qkv_b  = (const float*)d_in[4];
    const float* proj_w = (const float*)d_in[5];
    const float* proj_b = (const float*)d_in[6];
    float* out = (float*)d_out;

    cudaFuncSetAttribute(mm_gemm<0>, cudaFuncAttributeMaxDynamicSharedMemorySize, DYN_SMEM);
    cudaFuncSetAttribute(mm_gemm<1>, cudaFuncAttributeMaxDynamicSharedMemorySize, DYN_SMEM);
    cudaFuncSetAttribute(mm_gemm<2>, cudaFuncAttributeMaxDynamicSharedMemorySize, DYN_SMEM);
    cudaFuncSetAttribute(mm_gemm<3>, cudaFuncAttributeMaxDynamicSharedMemorySize, DYN_SMEM);

    f16 *h2, *w1, *w2, *q2, *k2, *v2, *p2, *ao2; float* sc;
    cudaGetSymbolAddress((void**)&h2,  g_h2);
    cudaGetSymbolAddress((void**)&w1,  g_w1);
    cudaGetSymbolAddress((void**)&w2,  g_w2);
    cudaGetSymbolAddress((void**)&q2,  g_q2);
    cudaGetSymbolAddress((void**)&k2,  g_k2);
    cudaGetSymbolAddress((void**)&v2,  g_v2);
    cudaGetSymbolAddress((void**)&p2,  g_p2);
    cudaGetSymbolAddress((void**)&ao2, g_ao2);
    cudaGetSymbolAddress((void**)&sc,  g_sc);

    // 1. weight convert
    wconv<<<(2048*512 + 255)/256, 256>>>(qkv_w, proj_w);

    // 2. fused GroupNorm stats
    gn_stats<<<dim3(64, BB), 256>>>(x);

    // 3. normalize + transpose (fp16)
    norm_split<<<dim3(SS/32, CC/32, BB), dim3(32, 8)>>>(x, gn_w, gn_b);

    // 4. QKV GEMM: M=16384, N=1536, K=512 (Q prescaled)  <-- profiled slot
    mm_gemm<0><<<dim3(12, 128, 1), 256, DYN_SMEM>>>(
        h2, 512, 0LL, w1, 512, 0LL,
        nullptr, qkv_b, nullptr, 0.044194173824159216f, 512);

    // 5. scores = Q K^T (Q prescaled), batched: K=512
    mm_gemm<1><<<dim3(8, 8, BB), 256, DYN_SMEM>>>(
        q2, 512, 1024LL*512, k2, 512, 1024LL*512, sc,
        nullptr, nullptr, 1.f, 512);

    // 6. softmax
    softmax_rows<<<BB*SS, 256>>>(sc);

    // 7. attn @ V: M=1024, N=512, K=1024, batched
    mm_gemm<2><<<dim3(4, 8, BB), 256, DYN_SMEM>>>(
        p2, 1024, 1024LL*1024, v2, 1024, 512LL*1024, nullptr,
        nullptr, nullptr, 1.f, 1024);

    // 8. proj^T + bias + residual -> NCHW out: M=512 (c), N=16384 (b*s), K=512
    mm_gemm<3><<<dim3(128, 4, 1), 256, DYN_SMEM>>>(
        w2, 512, 0LL, ao2, 512, 0LL, out, proj_b, x, 1.f, 512);
}

// round 14
// speedup vs baseline: 1.2642x; 1.0117x over previous
#include <cuda_runtime.h>
#include <cuda_fp16.h>
#include <cstdint>
#include <math.h>

#define BB 16
#define CC 512
#define SS 1024
#define PER_B (CC*SS)

typedef __half f16;

// ---------------- scratch (__device__ globals; no allocs) ----------------
__device__ float g_psum[BB*64], g_psq[BB*64], g_stats[BB*2];
__device__ unsigned g_ctr;
__device__ f16  g_h2 [(size_t)BB*SS*512];    // norm'd [B*S, C] fp16 (A-side)
__device__ f16  g_w1 [1536*512];             // qkv_w fp16 (B-side)
__device__ f16  g_w2 [512*512];              // proj_w fp16 (A-side for proj)
__device__ f16  g_q2 [(size_t)BB*SS*512];    // Q*scale fp16 (A-side)
__device__ f16  g_k2 [(size_t)BB*SS*512];    // K fp16 (B-side)
__device__ f16  g_v2 [(size_t)BB*CC*1024];   // V transposed [B,C,S] fp16 (B-side)
__device__ f16  g_p2 [(size_t)BB*SS*1024];   // probs [B*S, S] fp16 (A-side)
__device__ f16  g_ao2[(size_t)BB*SS*512];    // attn out fp16 (B-side for proj)
__device__ f16  g_scf[(size_t)BB*SS*SS];     // scores fp16

// ---------------- helpers ----------------
__device__ __forceinline__ uint32_t smem_u32(const void* p) {
    uint32_t a;
    asm("{ .reg .u64 t; cvta.to.shared.u64 t, %1; cvt.u32.u64 %0, t; }" : "=r"(a) : "l"(p));
    return a;
}
#define CP_ASYNC16(dst, src) \
    asm volatile("cp.async.cg.shared.global [%0], [%1], 16;" :: "r"(dst), "l"(src) : "memory")
#define CP_COMMIT() asm volatile("cp.async.commit_group;" ::: "memory")
#define CP_WAIT0()  asm volatile("cp.async.wait_group 0;" ::: "memory")
#define CP_WAIT1()  asm volatile("cp.async.wait_group 1;" ::: "memory")
#define CP_WAIT2()  asm volatile("cp.async.wait_group 2;" ::: "memory")
#define LDM_X4(r0,r1,r2,r3,addr) \
    asm volatile("ldmatrix.sync.aligned.m8n8.x4.shared.b16 {%0,%1,%2,%3}, [%4];" \
        : "=r"(r0),"=r"(r1),"=r"(r2),"=r"(r3) : "r"(addr))
#define MMA16816(d, a, b0, b1) \
    asm volatile("mma.sync.aligned.m16n8k16.row.col.f32.f16.f16.f32 " \
        "{%0,%1,%2,%3}, {%4,%5,%6,%7}, {%8,%9}, {%0,%1,%2,%3};" \
        : "+f"((d)[0]), "+f"((d)[1]), "+f"((d)[2]), "+f"((d)[3]) \
        : "r"((a)[0]), "r"((a)[1]), "r"((a)[2]), "r"((a)[3]), "r"(b0), "r"(b1))

// ---------------- weight convert (plain fp16) ----------------
__global__ void wconv(const float* __restrict__ w1s, const float* __restrict__ w2s) {
    int i = blockIdx.x * 256 + threadIdx.x;
    if (i < 2048*512) {
        if (i < 1536*512) g_w1[i] = __float2half_rn(w1s[i]);
        else              g_w2[i - 1536*512] = __float2half_rn(w2s[i - 1536*512]);
    }
}

// ---------------- fused GroupNorm stats ----------------
__global__ void gn_stats(const float* __restrict__ x) {
    int b = blockIdx.y, chunk = blockIdx.x, t = threadIdx.x;
    const float* p = x + (size_t)b*PER_B + (size_t)chunk*8192;
    float s = 0.f, q = 0.f;
#pragma unroll
    for (int i = 0; i < 32; i++) { float v = p[t + i*256]; s += v; q += v*v; }
    __shared__ float ss_[8], sq_[8];
    for (int o = 16; o > 0; o >>= 1) {
        s += __shfl_down_sync(0xffffffffu, s, o);
        q += __shfl_down_sync(0xffffffffu, q, o);
    }
    if ((t & 31) == 0) { ss_[t >> 5] = s; sq_[t >> 5] = q; }
    __syncthreads();
    __shared__ int isLast;
    if (t == 0) {
        float S2 = 0.f, Q2 = 0.f;
#pragma unroll
        for (int i = 0; i < 8; i++) { S2 += ss_[i]; Q2 += sq_[i]; }
        g_psum[b*64 + chunk] = S2; g_psq[b*64 + chunk] = Q2;
        __threadfence();
        unsigned v = atomicAdd(&g_ctr, 1u);
        isLast = (v == 64u*BB - 1u);
    }
    __syncthreads();
    if (isLast) {
        if (t < BB) {
            float s2 = 0.f, q2 = 0.f;
            for (int i = 0; i < 64; i++) { s2 += g_psum[t*64+i]; q2 += g_psq[t*64+i]; }
            float mean = s2 * (1.f/(float)PER_B);
            float var  = q2 * (1.f/(float)PER_B) - mean*mean;
            g_stats[2*t] = mean; g_stats[2*t+1] = rsqrtf(var + 1e-5f);
        }
        if (t == 0) g_ctr = 0u;
    }
}

// ---------------- normalize + transpose -> g_h2 [B*S, C] fp16 ----------------
__global__ void norm_split(const float* __restrict__ x,
                           const float* __restrict__ gw,
                           const float* __restrict__ gb) {
    __shared__ float tile[32][33];
    int b = blockIdx.z;
    int s0 = blockIdx.x * 32, c0 = blockIdx.y * 32;
    int tx = threadIdx.x, ty = threadIdx.y;
    const float* xp = x + (size_t)b * PER_B;
#pragma unroll
    for (int i = 0; i < 4; i++) {
        int c = c0 + ty + i*8;
        tile[ty + i*8][tx] = xp[(size_t)c*SS + s0 + tx];
    }
    __syncthreads();
    float mean = g_stats[2*b], inv = g_stats[2*b+1];
    int c = c0 + tx;
    float w  = gw[c] * inv;
    float bias = gb[c] - mean * w;
#pragma unroll
    for (int i = 0; i < 4; i++) {
        int s = s0 + ty + i*8;
        float v = tile[tx][ty + i*8] * w + bias;
        g_h2[((size_t)b*SS + s) * 512 + c] = __float2half_rn(v);
    }
}

// ---------------- HMMA GEMM: 128x128 CTA, 8 warps (32x64 each), BK=32, 4-stage ----------------
// NT: out[m,n] = sum_k A[m,k]*B[n,k]
// EPI: 0 = QKV out (Q scaled, K direct, V staged transpose), 1 = scores fp16 (Q prescaled),
//      2 = AV out, 3 = proj^T +bias+resid
#define STAGE_BYTES 20480
#define DYN_SMEM 81920

__device__ __forceinline__ void prefetch_tile(char* smem, int stage,
    const f16* __restrict__ A, int lda, const f16* __restrict__ B, int ldb,
    int m0, int n0, int k0, int tid)
{
    char* as = smem + stage*STAGE_BYTES;
    char* bs = as + 10240;
    int row = tid >> 1, seg = tid & 1;
    const f16* ag = A + (size_t)(m0 + row)*lda + k0 + seg*16;
    const f16* bg = B + (size_t)(n0 + row)*ldb + k0 + seg*16;
    uint32_t asw = smem_u32(as + row*80 + seg*32);
    uint32_t bsw = smem_u32(bs + row*80 + seg*32);
    CP_ASYNC16(asw,      (const void*)ag);
    CP_ASYNC16(asw + 16, (const void*)(ag + 8));
    CP_ASYNC16(bsw,      (const void*)bg);
    CP_ASYNC16(bsw + 16, (const void*)(bg + 8));
}

template<int EPI>
__global__ __launch_bounds__(256, 2)
void mm_gemm(const f16* __restrict__ A, int lda, long long sA,
             const f16* __restrict__ B, int ldb, long long sB,
             float* __restrict__ Out,
             const float* __restrict__ bias,
             const float* __restrict__ resid,
             float scale, int K)
{
    extern __shared__ char smem[];
    int tid = threadIdx.x, lane = tid & 31, wid = tid >> 5;
    int wm = wid >> 1, wn = wid & 1;
    int z = blockIdx.z;
    int m0 = blockIdx.y * 128, n0 = blockIdx.x * 128;
    A += (size_t)z * sA;
    B += (size_t)z * sB;

    float acc[2][8][4];
#pragma unroll
    for (int i = 0; i < 2; i++)
#pragma unroll
        for (int j = 0; j < 8; j++)
#pragma unroll
            for (int r = 0; r < 4; r++) acc[i][j][r] = 0.f;

    uint32_t a_off = (uint32_t)((wm*32 + (lane & 15)) * 80 + (lane >> 4) * 16);
    uint32_t b_off = (uint32_t)((wn*64 + (lane & 7) + ((lane >> 4) << 3)) * 80
                                + ((lane >> 3) & 1) * 16);
    uint32_t smem_base = smem_u32(smem);

    int nch = K >> 5;
#pragma unroll
    for (int p = 0; p < 3; p++) {
        if (p < nch) { prefetch_tile(smem, p, A, lda, B, ldb, m0, n0, p*32, tid); CP_COMMIT(); }
    }

    int st = 0;
    for (int c = 0; c < nch; c++) {
        int rem = nch - 1 - c;
        if (rem >= 2) CP_WAIT2(); else if (rem == 1) CP_WAIT1(); else CP_WAIT0();
        __syncthreads();
        if (c + 3 < nch) {
            prefetch_tile(smem, (st + 3) & 3, A, lda, B, ldb, m0, n0, (c+3)*32, tid);
            CP_COMMIT();
        }

        uint32_t as_b = smem_base + st*STAGE_BYTES + a_off;
        uint32_t bs_b = smem_base + st*STAGE_BYTES + 10240 + b_off;
#pragma unroll
        for (int ks = 0; ks < 2; ks++) {
            uint32_t a[2][4], b[4][4];
#pragma unroll
            for (int mf = 0; mf < 2; mf++)
                LDM_X4(a[mf][0], a[mf][1], a[mf][2], a[mf][3], as_b + mf*1280 + ks*32);
#pragma unroll
            for (int nf2 = 0; nf2 < 4; nf2++)
                LDM_X4(b[nf2][0], b[nf2][1], b[nf2][2], b[nf2][3], bs_b + nf2*1280 + ks*32);
#pragma unroll
            for (int mf = 0; mf < 2; mf++)
#pragma unroll
                for (int nf = 0; nf < 8; nf++)
                    MMA16816(acc[mf][nf], a[mf], b[nf>>1][(nf&1)*2], b[nf>>1][(nf&1)*2+1]);
        }
        st = (st + 1) & 3;
    }

    int r4 = lane >> 2, cp = (lane & 3) * 2;

    if constexpr (EPI == 0) {
        if (n0 < 1024) {             // Q (scaled) / K direct half2 stores
            f16* dst = (n0 < 512) ? g_q2 : g_k2;
            int nbase = (n0 < 512) ? n0 : (n0 - 512);
            float sc = (n0 < 512) ? scale : 1.f;
#pragma unroll
            for (int mf = 0; mf < 2; mf++)
#pragma unroll
                for (int nf = 0; nf < 8; nf++) {
                    int rr = m0 + wm*32 + mf*16 + r4;
                    int cc = wn*64 + nf*8 + cp;
                    float b0 = bias[n0 + cc], b1 = bias[n0 + cc + 1];
                    *(__half2*)&dst[(size_t)rr * 512 + nbase + cc] =
                        __floats2half2_rn((acc[mf][nf][0] + b0)*sc, (acc[mf][nf][1] + b1)*sc);
                    *(__half2*)&dst[(size_t)(rr + 8) * 512 + nbase + cc] =
                        __floats2half2_rn((acc[mf][nf][2] + b0)*sc, (acc[mf][nf][3] + b1)*sc);
                }
        } else {                     // V: staged transpose -> [B,C,S]
            __syncthreads();
            float* tile = (float*)smem;
#pragma unroll
            for (int mf = 0; mf < 2; mf++)
#pragma unroll
                for (int nf = 0; nf < 8; nf++) {
                    int rr = wm*32 + mf*16 + r4, cc = wn*64 + nf*8 + cp;
                    tile[rr*132 + cc]       = acc[mf][nf][0];
                    tile[rr*132 + cc + 1]   = acc[mf][nf][1];
                    tile[(rr+8)*132 + cc]   = acc[mf][nf][2];
                    tile[(rr+8)*132 + cc+1] = acc[mf][nf][3];
                }
            __syncthreads();
            for (int idx = tid; idx < 16384; idx += 256) {
                int rt = idx & 127, ct = idx >> 7;
                float v = tile[rt*132 + ct] + bias[n0 + ct];
                int m = m0 + rt, b = m >> 10, s = m & 1023;
                int cg = n0 + ct - 1024;
                g_v2[((size_t)b*512 + cg) * 1024 + s] = __float2half_rn(v);
            }
        }
    } else if constexpr (EPI == 1) { // scores fp16 (Q prescaled)
        f16* op = g_scf + (size_t)z * SS * SS;
#pragma unroll
        for (int mf = 0; mf < 2; mf++)
#pragma unroll
            for (int nf = 0; nf < 8; nf++) {
                int rr = m0 + wm*32 + mf*16 + r4;
                int cc = n0 + wn*64 + nf*8 + cp;
                *(__half2*)&op[(size_t)rr * SS + cc] =
                    __floats2half2_rn(acc[mf][nf][0], acc[mf][nf][1]);
                *(__half2*)&op[(size_t)(rr + 8) * SS + cc] =
                    __floats2half2_rn(acc[mf][nf][2], acc[mf][nf][3]);
            }
    } else if constexpr (EPI == 2) { // AV direct half2
#pragma unroll
        for (int mf = 0; mf < 2; mf++)
#pragma unroll
            for (int nf = 0; nf < 8; nf++) {
                int rr = m0 + wm*32 + mf*16 + r4;
                int cc = n0 + wn*64 + nf*8 + cp;
                *(__half2*)&g_ao2[((size_t)z * SS + rr) * 512 + cc] =
                    __floats2half2_rn(acc[mf][nf][0], acc[mf][nf][1]);
                *(__half2*)&g_ao2[((size_t)z * SS + rr + 8) * 512 + cc] =
                    __floats2half2_rn(acc[mf][nf][2], acc[mf][nf][3]);
            }
    } else {                         // proj^T: m=c-dim, n=global s; +bias+resid
#pragma unroll
        for (int mf = 0; mf < 2; mf++) {
            int rr = m0 + wm*32 + mf*16 + r4;
            float bias_r  = bias[rr], bias_r8 = bias[rr + 8];
#pragma unroll
            for (int nf = 0; nf < 8; nf++) {
                int n = n0 + wn*64 + nf*8 + cp;
                int b = n >> 10, s = n & 1023;
                size_t o0 = ((size_t)b * 512 + rr) * 1024 + s;
                size_t o1 = ((size_t)b * 512 + rr + 8) * 1024 + s;
                float2 rv0 = *(const float2*)&resid[o0];
                float2 rv1 = *(const float2*)&resid[o1];
                float2 w0 = {acc[mf][nf][0] + bias_r  + rv0.x, acc[mf][nf][1] + bias_r  + rv0.y};
                float2 w1 = {acc[mf][nf][2] + bias_r8 + rv1.x, acc[mf][nf][3] + bias_r8 + rv1.y};
                *(float2*)&Out[o0] = w0;
                *(float2*)&Out[o1] = w1;
            }
        }
    }
}

// ---------------- softmax over 1024-wide fp16 rows, fp16 output ----------------
__global__ void softmax_rows() {
    const f16* row = g_scf + (size_t)blockIdx.x * SS;
    f16* orow = g_p2 + (size_t)blockIdx.x * 1024;
    int t = threadIdx.x;
    float v[4];
    {
        __half2 h0 = *(const __half2*)&row[t*2];
        __half2 h1 = *(const __half2*)&row[512 + t*2];
        float2 f0 = __half22float2(h0), f1 = __half22float2(h1);
        v[0] = f0.x; v[1] = f0.y; v[2] = f1.x; v[3] = f1.y;
    }
    float m = fmaxf(fmaxf(v[0], v[1]), fmaxf(v[2], v[3]));
    __shared__ float red[8];
    for (int o = 16; o > 0; o >>= 1) m = fmaxf(m, __shfl_xor_sync(0xffffffffu, m, o));
    if ((t & 31) == 0) red[t >> 5] = m;
    __syncthreads();
    float mm = fmaxf(fmaxf(fmaxf(red[0], red[1]), fmaxf(red[2], red[3])),
                     fmaxf(fmaxf(red[4], red[5]), fmaxf(red[6], red[7])));
    float s = 0.f;
#pragma unroll
    for (int i = 0; i < 4; i++) { v[i] = __expf(v[i] - mm); s += v[i]; }
    for (int o = 16; o > 0; o >>= 1) s += __shfl_xor_sync(0xffffffffu, s, o);
    __syncthreads();
    if ((t & 31) == 0) red[t >> 5] = s;
    __syncthreads();
    float tot = ((red[0]+red[1]) + (red[2]+red[3])) + ((red[4]+red[5]) + (red[6]+red[7]));
    float invs = 1.f / tot;
    *(__half2*)&orow[t*2]       = __floats2half2_rn(v[0] * invs, v[1] * invs);
    *(__half2*)&orow[512 + t*2] = __floats2half2_rn(v[2] * invs, v[3] * invs);
}

// ---------------- launch ----------------
extern "C" void kernel_launch(void* const* d_in, const int* in_sizes, int n_in,
                              void* d_out, int out_size) {
    const float* x      = (const float*)d_in[0];
    const float* gn_w   = (const float*)d_in[1];
    const float* gn_b   = (const float*)d_in[2];
    const float* qkv_w  = (const float*)d_in[3];
    const float* qkv_b  = (const float*)d_in[4];
    const float* proj_w = (const float*)d_in[5];
    const float* proj_b = (const float*)d_in[6];
    float* out = (float*)d_out;

    cudaFuncSetAttribute(mm_gemm<0>, cudaFuncAttributeMaxDynamicSharedMemorySize, DYN_SMEM);
    cudaFuncSetAttribute(mm_gemm<1>, cudaFuncAttributeMaxDynamicSharedMemorySize, DYN_SMEM);
    cudaFuncSetAttribute(mm_gemm<2>, cudaFuncAttributeMaxDynamicSharedMemorySize, DYN_SMEM);
    cudaFuncSetAttribute(mm_gemm<3>, cudaFuncAttributeMaxDynamicSharedMemorySize, DYN_SMEM);

    f16 *h2, *w1, *w2, *q2, *k2, *v2, *p2, *ao2;
    cudaGetSymbolAddress((void**)&h2,  g_h2);
    cudaGetSymbolAddress((void**)&w1,  g_w1);
    cudaGetSymbolAddress((void**)&w2,  g_w2);
    cudaGetSymbolAddress((void**)&q2,  g_q2);
    cudaGetSymbolAddress((void**)&k2,  g_k2);
    cudaGetSymbolAddress((void**)&v2,  g_v2);
    cudaGetSymbolAddress((void**)&p2,  g_p2);
    cudaGetSymbolAddress((void**)&ao2, g_ao2);

    // 1. weight convert
    wconv<<<(2048*512 + 255)/256, 256>>>(qkv_w, proj_w);

    // 2. fused GroupNorm stats
    gn_stats<<<dim3(64, BB), 256>>>(x);

    // 3. normalize + transpose (fp16)
    norm_split<<<dim3(SS/32, CC/32, BB), dim3(32, 8)>>>(x, gn_w, gn_b);

    // 4. QKV GEMM: M=16384, N=1536, K=512 (Q prescaled)  <-- profiled slot
    mm_gemm<0><<<dim3(12, 128, 1), 256, DYN_SMEM>>>(
        h2, 512, 0LL, w1, 512, 0LL,
        nullptr, qkv_b, nullptr, 0.044194173824159216f, 512);

    // 5. scores = Q K^T (Q prescaled) -> fp16, batched: K=512
    mm_gemm<1><<<dim3(8, 8, BB), 256, DYN_SMEM>>>(
        q2, 512, 1024LL*512, k2, 512, 1024LL*512, nullptr,
        nullptr, nullptr, 1.f, 512);

    // 6. softmax (fp16 in/out)
    softmax_rows<<<BB*SS, 256>>>();

    // 7. attn @ V: M=1024, N=512, K=1024, batched
    mm_gemm<2><<<dim3(4, 8, BB), 256, DYN_SMEM>>>(
        p2, 1024, 1024LL*1024, v2, 1024, 512LL*1024, nullptr,
        nullptr, nullptr, 1.f, 1024);

    // 8. proj^T + bias + residual -> NCHW out: M=512 (c), N=16384 (b*s), K=512
    mm_gemm<3><<<dim3(128, 4, 1), 256, DYN_SMEM>>>(
        w2, 512, 0LL, ao2, 512, 0LL, out, proj_b, x, 1.f, 512);
}

// round 15
// speedup vs baseline: 1.2830x; 1.0149x over previous
#include <cuda_runtime.h>
#include <cuda_fp16.h>
#include <cstdint>
#include <math.h>

#define BB 16
#define CC 512
#define SS 1024
#define PER_B (CC*SS)

typedef __half f16;

// ---------------- scratch (__device__ globals; no allocs) ----------------
__device__ float g_psum[BB*64], g_psq[BB*64], g_stats[BB*2];
__device__ unsigned g_ctr;
__device__ f16  g_h2 [(size_t)BB*SS*512];    // norm'd [B*S, C] fp16 (A-side)
__device__ f16  g_w1 [1536*512];             // qkv_w fp16 (B-side)
__device__ f16  g_w2 [512*512];              // proj_w fp16 (A-side for proj)
__device__ f16  g_q2 [(size_t)BB*SS*512];    // Q*scale fp16 (A-side)
__device__ f16  g_k2 [(size_t)BB*SS*512];    // K fp16 (B-side)
__device__ f16  g_v2 [(size_t)BB*CC*1024];   // V transposed [B,C,S] fp16 (B-side)
__device__ f16  g_p2 [(size_t)BB*SS*1024];   // probs [B*S, S] fp16 (A-side)
__device__ f16  g_ao2[(size_t)BB*SS*512];    // attn out fp16 (B-side for proj)
__device__ f16  g_scf[(size_t)BB*SS*SS];     // scores fp16

// ---------------- helpers ----------------
__device__ __forceinline__ uint32_t smem_u32(const void* p) {
    uint32_t a;
    asm("{ .reg .u64 t; cvta.to.shared.u64 t, %1; cvt.u32.u64 %0, t; }" : "=r"(a) : "l"(p));
    return a;
}
#define CP_ASYNC16(dst, src) \
    asm volatile("cp.async.cg.shared.global [%0], [%1], 16;" :: "r"(dst), "l"(src) : "memory")
#define CP_COMMIT() asm volatile("cp.async.commit_group;" ::: "memory")
#define CP_WAIT0()  asm volatile("cp.async.wait_group 0;" ::: "memory")
#define CP_WAIT1()  asm volatile("cp.async.wait_group 1;" ::: "memory")
#define CP_WAIT2()  asm volatile("cp.async.wait_group 2;" ::: "memory")
#define LDM_X4(r0,r1,r2,r3,addr) \
    asm volatile("ldmatrix.sync.aligned.m8n8.x4.shared.b16 {%0,%1,%2,%3}, [%4];" \
        : "=r"(r0),"=r"(r1),"=r"(r2),"=r"(r3) : "r"(addr))
#define MMA16816(d, a, b0, b1) \
    asm volatile("mma.sync.aligned.m16n8k16.row.col.f32.f16.f16.f32 " \
        "{%0,%1,%2,%3}, {%4,%5,%6,%7}, {%8,%9}, {%0,%1,%2,%3};" \
        : "+f"((d)[0]), "+f"((d)[1]), "+f"((d)[2]), "+f"((d)[3]) \
        : "r"((a)[0]), "r"((a)[1]), "r"((a)[2]), "r"((a)[3]), "r"(b0), "r"(b1))

// ---------------- fused GroupNorm stats + weight convert ----------------
// blocks [0,1024): GN partial+finalize; blocks [1024,2048): wconv float4
__global__ void gn_stats_wconv(const float* __restrict__ x,
                               const float* __restrict__ w1s,
                               const float* __restrict__ w2s) {
    int t = threadIdx.x;
    if (blockIdx.x >= 1024) {
        // weight convert: 1024 blocks x 256 threads x 1 float4 = 1048576 floats
        int i4 = (blockIdx.x - 1024) * 256 + t;          // float4 index
        int i = i4 * 4;
        float4 v;
        f16* dst;
        if (i < 1536*512) { v = *(const float4*)&w1s[i]; dst = g_w1 + i; }
        else              { v = *(const float4*)&w2s[i - 1536*512]; dst = g_w2 + (i - 1536*512); }
        *(__half2*)&dst[0] = __floats2half2_rn(v.x, v.y);
        *(__half2*)&dst[2] = __floats2half2_rn(v.z, v.w);
        return;
    }
    int b = blockIdx.x >> 6, chunk = blockIdx.x & 63;
    const float* p = x + (size_t)b*PER_B + (size_t)chunk*8192;
    float s = 0.f, q = 0.f;
#pragma unroll
    for (int i = 0; i < 32; i++) { float v = p[t + i*256]; s += v; q += v*v; }
    __shared__ float ss_[8], sq_[8];
    for (int o = 16; o > 0; o >>= 1) {
        s += __shfl_down_sync(0xffffffffu, s, o);
        q += __shfl_down_sync(0xffffffffu, q, o);
    }
    if ((t & 31) == 0) { ss_[t >> 5] = s; sq_[t >> 5] = q; }
    __syncthreads();
    __shared__ int isLast;
    if (t == 0) {
        float S2 = 0.f, Q2 = 0.f;
#pragma unroll
        for (int i = 0; i < 8; i++) { S2 += ss_[i]; Q2 += sq_[i]; }
        g_psum[b*64 + chunk] = S2; g_psq[b*64 + chunk] = Q2;
        __threadfence();
        unsigned v = atomicAdd(&g_ctr, 1u);
        isLast = (v == 64u*BB - 1u);
    }
    __syncthreads();
    if (isLast) {
        if (t < BB) {
            float s2 = 0.f, q2 = 0.f;
            for (int i = 0; i < 64; i++) { s2 += g_psum[t*64+i]; q2 += g_psq[t*64+i]; }
            float mean = s2 * (1.f/(float)PER_B);
            float var  = q2 * (1.f/(float)PER_B) - mean*mean;
            g_stats[2*t] = mean; g_stats[2*t+1] = rsqrtf(var + 1e-5f);
        }
        if (t == 0) g_ctr = 0u;
    }
}

// ---------------- normalize + transpose -> g_h2 [B*S, C] fp16 ----------------
__global__ void norm_split(const float* __restrict__ x,
                           const float* __restrict__ gw,
                           const float* __restrict__ gb) {
    __shared__ float tile[32][33];
    int b = blockIdx.z;
    int s0 = blockIdx.x * 32, c0 = blockIdx.y * 32;
    int tx = threadIdx.x, ty = threadIdx.y;
    const float* xp = x + (size_t)b * PER_B;
#pragma unroll
    for (int i = 0; i < 4; i++) {
        int c = c0 + ty + i*8;
        tile[ty + i*8][tx] = xp[(size_t)c*SS + s0 + tx];
    }
    __syncthreads();
    float mean = g_stats[2*b], inv = g_stats[2*b+1];
    int c = c0 + tx;
    float w  = gw[c] * inv;
    float bias = gb[c] - mean * w;
#pragma unroll
    for (int i = 0; i < 4; i++) {
        int s = s0 + ty + i*8;
        float v = tile[tx][ty + i*8] * w + bias;
        g_h2[((size_t)b*SS + s) * 512 + c] = __float2half_rn(v);
    }
}

// ---------------- HMMA GEMM: 128x128 CTA, 8 warps (32x64 each), BK=32, 4-stage ----------------
// NT: out[m,n] = sum_k A[m,k]*B[n,k]
// EPI: 0 = QKV out (Q scaled, K direct, V staged transpose), 1 = scores fp16 (Q prescaled),
//      2 = AV out, 3 = proj^T +bias+resid
#define STAGE_BYTES 20480
#define DYN_SMEM 81920

__device__ __forceinline__ void prefetch_tile(char* smem, int stage,
    const f16* __restrict__ A, int lda, const f16* __restrict__ B, int ldb,
    int m0, int n0, int k0, int tid)
{
    char* as = smem + stage*STAGE_BYTES;
    char* bs = as + 10240;
    int row = tid >> 1, seg = tid & 1;
    const f16* ag = A + (size_t)(m0 + row)*lda + k0 + seg*16;
    const f16* bg = B + (size_t)(n0 + row)*ldb + k0 + seg*16;
    uint32_t asw = smem_u32(as + row*80 + seg*32);
    uint32_t bsw = smem_u32(bs + row*80 + seg*32);
    CP_ASYNC16(asw,      (const void*)ag);
    CP_ASYNC16(asw + 16, (const void*)(ag + 8));
    CP_ASYNC16(bsw,      (const void*)bg);
    CP_ASYNC16(bsw + 16, (const void*)(bg + 8));
}

template<int EPI>
__global__ __launch_bounds__(256, 2)
void mm_gemm(const f16* __restrict__ A, int lda, long long sA,
             const f16* __restrict__ B, int ldb, long long sB,
             float* __restrict__ Out,
             const float* __restrict__ bias,
             const float* __restrict__ resid,
             float scale, int K)
{
    extern __shared__ char smem[];
    int tid = threadIdx.x, lane = tid & 31, wid = tid >> 5;
    int wm = wid >> 1, wn = wid & 1;
    int z = blockIdx.z;
    int m0 = blockIdx.y * 128, n0 = blockIdx.x * 128;
    A += (size_t)z * sA;
    B += (size_t)z * sB;

    float acc[2][8][4];
#pragma unroll
    for (int i = 0; i < 2; i++)
#pragma unroll
        for (int j = 0; j < 8; j++)
#pragma unroll
            for (int r = 0; r < 4; r++) acc[i][j][r] = 0.f;

    uint32_t a_off = (uint32_t)((wm*32 + (lane & 15)) * 80 + (lane >> 4) * 16);
    uint32_t b_off = (uint32_t)((wn*64 + (lane & 7) + ((lane >> 4) << 3)) * 80
                                + ((lane >> 3) & 1) * 16);
    uint32_t smem_base = smem_u32(smem);

    int nch = K >> 5;
#pragma unroll
    for (int p = 0; p < 3; p++) {
        if (p < nch) { prefetch_tile(smem, p, A, lda, B, ldb, m0, n0, p*32, tid); CP_COMMIT(); }
    }

    int st = 0;
    for (int c = 0; c < nch; c++) {
        int rem = nch - 1 - c;
        if (rem >= 2) CP_WAIT2(); else if (rem == 1) CP_WAIT1(); else CP_WAIT0();
        __syncthreads();
        if (c + 3 < nch) {
            prefetch_tile(smem, (st + 3) & 3, A, lda, B, ldb, m0, n0, (c+3)*32, tid);
            CP_COMMIT();
        }

        uint32_t as_b = smem_base + st*STAGE_BYTES + a_off;
        uint32_t bs_b = smem_base + st*STAGE_BYTES + 10240 + b_off;
#pragma unroll
        for (int ks = 0; ks < 2; ks++) {
            uint32_t a[2][4], b[4][4];
#pragma unroll
            for (int mf = 0; mf < 2; mf++)
                LDM_X4(a[mf][0], a[mf][1], a[mf][2], a[mf][3], as_b + mf*1280 + ks*32);
#pragma unroll
            for (int nf2 = 0; nf2 < 4; nf2++)
                LDM_X4(b[nf2][0], b[nf2][1], b[nf2][2], b[nf2][3], bs_b + nf2*1280 + ks*32);
#pragma unroll
            for (int mf = 0; mf < 2; mf++)
#pragma unroll
                for (int nf = 0; nf < 8; nf++)
                    MMA16816(acc[mf][nf], a[mf], b[nf>>1][(nf&1)*2], b[nf>>1][(nf&1)*2+1]);
        }
        st = (st + 1) & 3;
    }

    int r4 = lane >> 2, cp = (lane & 3) * 2;

    if constexpr (EPI == 0) {
        if (n0 < 1024) {             // Q (scaled) / K direct half2 stores
            f16* dst = (n0 < 512) ? g_q2 : g_k2;
            int nbase = (n0 < 512) ? n0 : (n0 - 512);
            float sc = (n0 < 512) ? scale : 1.f;
#pragma unroll
            for (int mf = 0; mf < 2; mf++)
#pragma unroll
                for (int nf = 0; nf < 8; nf++) {
                    int rr = m0 + wm*32 + mf*16 + r4;
                    int cc = wn*64 + nf*8 + cp;
                    float b0 = bias[n0 + cc], b1 = bias[n0 + cc + 1];
                    *(__half2*)&dst[(size_t)rr * 512 + nbase + cc] =
                        __floats2half2_rn((acc[mf][nf][0] + b0)*sc, (acc[mf][nf][1] + b1)*sc);
                    *(__half2*)&dst[(size_t)(rr + 8) * 512 + nbase + cc] =
                        __floats2half2_rn((acc[mf][nf][2] + b0)*sc, (acc[mf][nf][3] + b1)*sc);
                }
        } else {                     // V: staged transpose -> [B,C,S]
            __syncthreads();
            float* tile = (float*)smem;
#pragma unroll
            for (int mf = 0; mf < 2; mf++)
#pragma unroll
                for (int nf = 0; nf < 8; nf++) {
                    int rr = wm*32 + mf*16 + r4, cc = wn*64 + nf*8 + cp;
                    tile[rr*132 + cc]       = acc[mf][nf][0];
                    tile[rr*132 + cc + 1]   = acc[mf][nf][1];
                    tile[(rr+8)*132 + cc]   = acc[mf][nf][2];
                    tile[(rr+8)*132 + cc+1] = acc[mf][nf][3];
                }
            __syncthreads();
            for (int idx = tid; idx < 16384; idx += 256) {
                int rt = idx & 127, ct = idx >> 7;
                float v = tile[rt*132 + ct] + bias[n0 + ct];
                int m = m0 + rt, b = m >> 10, s = m & 1023;
                int cg = n0 + ct - 1024;
                g_v2[((size_t)b*512 + cg) * 1024 + s] = __float2half_rn(v);
            }
        }
    } else if constexpr (EPI == 1) { // scores fp16 (Q prescaled)
        f16* op = g_scf + (size_t)z * SS * SS;
#pragma unroll
        for (int mf = 0; mf < 2; mf++)
#pragma unroll
            for (int nf = 0; nf < 8; nf++) {
                int rr = m0 + wm*32 + mf*16 + r4;
                int cc = n0 + wn*64 + nf*8 + cp;
                *(__half2*)&op[(size_t)rr * SS + cc] =
                    __floats2half2_rn(acc[mf][nf][0], acc[mf][nf][1]);
                *(__half2*)&op[(size_t)(rr + 8) * SS + cc] =
                    __floats2half2_rn(acc[mf][nf][2], acc[mf][nf][3]);
            }
    } else if constexpr (EPI == 2) { // AV direct half2
#pragma unroll
        for (int mf = 0; mf < 2; mf++)
#pragma unroll
            for (int nf = 0; nf < 8; nf++) {
                int rr = m0 + wm*32 + mf*16 + r4;
                int cc = n0 + wn*64 + nf*8 + cp;
                *(__half2*)&g_ao2[((size_t)z * SS + rr) * 512 + cc] =
                    __floats2half2_rn(acc[mf][nf][0], acc[mf][nf][1]);
                *(__half2*)&g_ao2[((size_t)z * SS + rr + 8) * 512 + cc] =
                    __floats2half2_rn(acc[mf][nf][2], acc[mf][nf][3]);
            }
    } else {                         // proj^T: m=c-dim, n=global s; +bias+resid
#pragma unroll
        for (int mf = 0; mf < 2; mf++) {
            int rr = m0 + wm*32 + mf*16 + r4;
            float bias_r  = bias[rr], bias_r8 = bias[rr + 8];
#pragma unroll
            for (int nf = 0; nf < 8; nf++) {
                int n = n0 + wn*64 + nf*8 + cp;
                int b = n >> 10, s = n & 1023;
                size_t o0 = ((size_t)b * 512 + rr) * 1024 + s;
                size_t o1 = ((size_t)b * 512 + rr + 8) * 1024 + s;
                float2 rv0 = *(const float2*)&resid[o0];
                float2 rv1 = *(const float2*)&resid[o1];
                float2 w0 = {acc[mf][nf][0] + bias_r  + rv0.x, acc[mf][nf][1] + bias_r  + rv0.y};
                float2 w1 = {acc[mf][nf][2] + bias_r8 + rv1.x, acc[mf][nf][3] + bias_r8 + rv1.y};
                *(float2*)&Out[o0] = w0;
                *(float2*)&Out[o1] = w1;
            }
        }
    }
}

// ---------------- softmax over 1024-wide fp16 rows, fp16 output ----------------
__global__ void softmax_rows() {
    const f16* row = g_scf + (size_t)blockIdx.x * SS;
    f16* orow = g_p2 + (size_t)blockIdx.x * 1024;
    int t = threadIdx.x;
    float v[4];
    {
        __half2 h0 = *(const __half2*)&row[t*2];
        __half2 h1 = *(const __half2*)&row[512 + t*2];
        float2 f0 = __half22float2(h0), f1 = __half22float2(h1);
        v[0] = f0.x; v[1] = f0.y; v[2] = f1.x; v[3] = f1.y;
    }
    float m = fmaxf(fmaxf(v[0], v[1]), fmaxf(v[2], v[3]));
    __shared__ float red[8];
    for (int o = 16; o > 0; o >>= 1) m = fmaxf(m, __shfl_xor_sync(0xffffffffu, m, o));
    if ((t & 31) == 0) red[t >> 5] = m;
    __syncthreads();
    float mm = fmaxf(fmaxf(fmaxf(red[0], red[1]), fmaxf(red[2], red[3])),
                     fmaxf(fmaxf(red[4], red[5]), fmaxf(red[6], red[7])));
    float s = 0.f;
#pragma unroll
    for (int i = 0; i < 4; i++) { v[i] = __expf(v[i] - mm); s += v[i]; }
    for (int o = 16; o > 0; o >>= 1) s += __shfl_xor_sync(0xffffffffu, s, o);
    __syncthreads();
    if ((t & 31) == 0) red[t >> 5] = s;
    __syncthreads();
    float tot = ((red[0]+red[1]) + (red[2]+red[3])) + ((red[4]+red[5]) + (red[6]+red[7]));
    float invs = 1.f / tot;
    *(__half2*)&orow[t*2]       = __floats2half2_rn(v[0] * invs, v[1] * invs);
    *(__half2*)&orow[512 + t*2] = __floats2half2_rn(v[2] * invs, v[3] * invs);
}

// ---------------- launch ----------------
extern "C" void kernel_launch(void* const* d_in, const int* in_sizes, int n_in,
                              void* d_out, int out_size) {
    const float* x      = (const float*)d_in[0];
    const float* gn_w   = (const float*)d_in[1];
    const float* gn_b   = (const float*)d_in[2];
    const float* qkv_w  = (const float*)d_in[3];
    const float* qkv_b  = (const float*)d_in[4];
    const float* proj_w = (const float*)d_in[5];
    const float* proj_b = (const float*)d_in[6];
    float* out = (float*)d_out;

    cudaFuncSetAttribute(mm_gemm<0>, cudaFuncAttributeMaxDynamicSharedMemorySize, DYN_SMEM);
    cudaFuncSetAttribute(mm_gemm<1>, cudaFuncAttributeMaxDynamicSharedMemorySize, DYN_SMEM);
    cudaFuncSetAttribute(mm_gemm<2>, cudaFuncAttributeMaxDynamicSharedMemorySize, DYN_SMEM);
    cudaFuncSetAttribute(mm_gemm<3>, cudaFuncAttributeMaxDynamicSharedMemorySize, DYN_SMEM);

    f16 *h2, *w1, *w2, *q2, *k2, *v2, *p2, *ao2;
    cudaGetSymbolAddress((void**)&h2,  g_h2);
    cudaGetSymbolAddress((void**)&w1,  g_w1);
    cudaGetSymbolAddress((void**)&w2,  g_w2);
    cudaGetSymbolAddress((void**)&q2,  g_q2);
    cudaGetSymbolAddress((void**)&k2,  g_k2);
    cudaGetSymbolAddress((void**)&v2,  g_v2);
    cudaGetSymbolAddress((void**)&p2,  g_p2);
    cudaGetSymbolAddress((void**)&ao2, g_ao2);

    // 1. fused GroupNorm stats + weight convert (blocks 0-1023 GN, 1024-2047 wconv)
    gn_stats_wconv<<<2048, 256>>>(x, qkv_w, proj_w);

    // 2. normalize + transpose (fp16)
    norm_split<<<dim3(SS/32, CC/32, BB), dim3(32, 8)>>>(x, gn_w, gn_b);

    // 3. QKV GEMM: M=16384, N=1536, K=512 (Q prescaled)
    mm_gemm<0><<<dim3(12, 128, 1), 256, DYN_SMEM>>>(
        h2, 512, 0LL, w1, 512, 0LL,
        nullptr, qkv_b, nullptr, 0.044194173824159216f, 512);

    // 4. scores = Q K^T (Q prescaled) -> fp16, batched: K=512
    mm_gemm<1><<<dim3(8, 8, BB), 256, DYN_SMEM>>>(
        q2, 512, 1024LL*512, k2, 512, 1024LL*512, nullptr,
        nullptr, nullptr, 1.f, 512);

    // 5. softmax (fp16 in/out)
    softmax_rows<<<BB*SS, 256>>>();

    // 6. attn @ V: M=1024, N=512, K=1024, batched
    mm_gemm<2><<<dim3(4, 8, BB), 256, DYN_SMEM>>>(
        p2, 1024, 1024LL*1024, v2, 1024, 512LL*1024, nullptr,
        nullptr, nullptr, 1.f, 1024);

    // 7. proj^T + bias + residual -> NCHW out: M=512 (c), N=16384 (b*s), K=512
    mm_gemm<3><<<dim3(128, 4, 1), 256, DYN_SMEM>>>(
        w2, 512, 0LL, ao2, 512, 0LL, out, proj_b, x, 1.f, 512);
}